// round 8
// baseline (speedup 1.0000x reference)
#include <cuda_runtime.h>
#include <cstdio>
#include <cstdlib>
#include <cstdint>
#include <cmath>

#define Nn   100000
#define Ee   1600000
#define INF  128
#define Hd   64
#define Ll   8
#define OUTD 40

// ---------------- scratch (static device globals; no allocation) ----------------
__device__ int   g_deg[Nn];
__device__ float g_dis[Nn];
__device__ int   g_rowptr[Nn + 1];
__device__ int   g_cursor[Nn];
__device__ __align__(16) int2  g_ew[Ee];            // {src, float_bits(norm)}
__device__ int   g_bsum[128];
__device__ __align__(16) float g_tmp[(size_t)Nn * Hd];  // h @ W (pre-aggregation)
__device__ __align__(16) float g_h[(size_t)Nn * Hd];    // layer output
__device__ int   g_is64;

// ---------------- dtype probe: int64 vs int32 edge_index ----------------
__global__ void k_detect(const unsigned int* __restrict__ p) {
    __shared__ unsigned int s;
    if (threadIdx.x == 0) s = 0u;
    __syncthreads();
    unsigned int v = 0u;
    for (int e = threadIdx.x; e < 2048; e += 256) v |= p[2 * e + 1];
    atomicOr(&s, v);
    __syncthreads();
    if (threadIdx.x == 0) g_is64 = (s == 0u) ? 1 : 0;
}

__device__ __forceinline__ int ld_src(const int* p, int e) {
    return g_is64 ? p[2 * e] : p[e];
}
__device__ __forceinline__ int ld_dst(const int* p, int e) {
    return g_is64 ? p[2 * Ee + 2 * e] : p[Ee + e];
}

// ---------------- degree / normalization ----------------
__global__ void k_init_deg() {
    int i = blockIdx.x * 256 + threadIdx.x;
    if (i < Nn) g_deg[i] = 1;  // self loop
}

__global__ void k_count(const int* __restrict__ ei) {
    int e = blockIdx.x * 256 + threadIdx.x;
    if (e < Ee) atomicAdd(&g_deg[ld_dst(ei, e)], 1);
}

__global__ void k_dis() {
    int i = blockIdx.x * 256 + threadIdx.x;
    if (i < Nn) g_dis[i] = rsqrtf((float)g_deg[i]);
}

// ---------------- CSR build: exclusive scan of (deg-1) ----------------
__global__ void k_scan_block() {
    __shared__ int s[1024];
    int i = blockIdx.x * 1024 + threadIdx.x;
    int v = (i < Nn) ? (g_deg[i] - 1) : 0;
    s[threadIdx.x] = v;
    __syncthreads();
    for (int off = 1; off < 1024; off <<= 1) {
        int t = (threadIdx.x >= off) ? s[threadIdx.x - off] : 0;
        __syncthreads();
        s[threadIdx.x] += t;
        __syncthreads();
    }
    if (i < Nn) g_rowptr[i] = s[threadIdx.x] - v;  // local exclusive
    if (threadIdx.x == 1023) g_bsum[blockIdx.x] = s[1023];
}

__global__ void k_scan_bsum(int nb) {
    __shared__ int s[128];
    int v = (threadIdx.x < nb) ? g_bsum[threadIdx.x] : 0;
    s[threadIdx.x] = v;
    __syncthreads();
    for (int off = 1; off < 128; off <<= 1) {
        int t = (threadIdx.x >= off) ? s[threadIdx.x - off] : 0;
        __syncthreads();
        s[threadIdx.x] += t;
        __syncthreads();
    }
    if (threadIdx.x < nb) g_bsum[threadIdx.x] = s[threadIdx.x] - v;  // exclusive
}

__global__ void k_add_off() {
    int i = blockIdx.x * 1024 + threadIdx.x;
    if (i < Nn) {
        int r = g_rowptr[i] + g_bsum[blockIdx.x];
        g_rowptr[i] = r;
        g_cursor[i] = r;
    }
    if (i == 0) g_rowptr[Nn] = Ee;
}

__global__ void k_fill(const int* __restrict__ ei) {
    int e = blockIdx.x * 256 + threadIdx.x;
    if (e >= Ee) return;
    int s = ld_src(ei, e);
    int d = ld_dst(ei, e);
    int p = atomicAdd(&g_cursor[d], 1);
    float wt = g_dis[s] * g_dis[d];
    g_ew[p] = make_int2(s, __float_as_int(wt));
}

// ---------------- dense GEMM: C[N x ODIM] (+)= A[N x K] * B[K x ODIM] ----------------
template <int K, int ODIM, bool ACCUM>
__global__ void k_gemm(const float* __restrict__ A, const float* __restrict__ B,
                       float* __restrict__ C) {
    constexpr int KT = 32;
    __shared__ float sA[128][KT + 1];
    __shared__ float sB[KT][64];
    const int row0 = blockIdx.x * 128;
    const int tid = threadIdx.x;
    const int tr = tid >> 4;   // 0..15
    const int tc = tid & 15;   // 0..15
    float acc[8][4];
#pragma unroll
    for (int i = 0; i < 8; i++)
#pragma unroll
        for (int j = 0; j < 4; j++) acc[i][j] = 0.f;

    for (int k0 = 0; k0 < K; k0 += KT) {
#pragma unroll
        for (int t = 0; t < 4; t++) {
            int fi = tid + t * 256;
            int r = fi >> 3, c4 = fi & 7;
            float4 v = make_float4(0.f, 0.f, 0.f, 0.f);
            if (row0 + r < Nn)
                v = *(const float4*)&A[(size_t)(row0 + r) * K + k0 + c4 * 4];
            sA[r][c4 * 4 + 0] = v.x;
            sA[r][c4 * 4 + 1] = v.y;
            sA[r][c4 * 4 + 2] = v.z;
            sA[r][c4 * 4 + 3] = v.w;
        }
#pragma unroll
        for (int t = 0; t < 8; t++) {
            int fi = tid + t * 256;
            int kk = fi >> 6, c = fi & 63;
            sB[kk][c] = (c < ODIM) ? B[(k0 + kk) * ODIM + c] : 0.f;
        }
        __syncthreads();
#pragma unroll
        for (int kk = 0; kk < KT; kk++) {
            float a[8], b[4];
#pragma unroll
            for (int i = 0; i < 8; i++) a[i] = sA[tr + 16 * i][kk];
#pragma unroll
            for (int j = 0; j < 4; j++) b[j] = sB[kk][tc + 16 * j];
#pragma unroll
            for (int i = 0; i < 8; i++)
#pragma unroll
                for (int j = 0; j < 4; j++) acc[i][j] += a[i] * b[j];
        }
        __syncthreads();
    }
#pragma unroll
    for (int i = 0; i < 8; i++) {
        int r = row0 + tr + 16 * i;
        if (r >= Nn) continue;
#pragma unroll
        for (int j = 0; j < 4; j++) {
            int c = tc + 16 * j;
            if (c < ODIM) {
                if (ACCUM)
                    C[(size_t)r * ODIM + c] += acc[i][j];
                else
                    C[(size_t)r * ODIM + c] = acc[i][j];
            }
        }
    }
}

// ---------------- sparse aggregation: h = relu(A_hat * tmp + b) ----------------
__global__ void k_aggregate(const float* __restrict__ bias) {
    int node = blockIdx.x * (blockDim.x >> 5) + (threadIdx.x >> 5);
    if (node >= Nn) return;
    int lane = threadIdx.x & 31;
    float ax = 0.f, ay = 0.f;
    int beg = g_rowptr[node], end = g_rowptr[node + 1];
    for (int j = beg; j < end; j++) {
        int2 e = __ldg(&g_ew[j]);
        float wt = __int_as_float(e.y);
        float2 v = *(const float2*)&g_tmp[(size_t)e.x * Hd + lane * 2];
        ax += wt * v.x;
        ay += wt * v.y;
    }
    float d = g_dis[node];
    float sw = d * d;  // self-loop norm
    float2 v = *(const float2*)&g_tmp[(size_t)node * Hd + lane * 2];
    ax += sw * v.x;
    ay += sw * v.y;
    ax += bias[lane * 2];
    ay += bias[lane * 2 + 1];
    float2 r;
    r.x = fmaxf(ax, 0.f);
    r.y = fmaxf(ay, 0.f);
    *(float2*)&g_h[(size_t)node * Hd + lane * 2] = r;
}

// ---------------- output init: out = lin_b broadcast ----------------
__global__ void k_init_out(float* __restrict__ out, const float* __restrict__ lin_b, int n) {
    int i = blockIdx.x * 256 + threadIdx.x;
    if (i < n) out[i] = lin_b[i % OUTD];
}

extern "C" void kernel_launch(void* const* d_in, const int* in_sizes, int n_in,
                              void* d_out, int out_size) {
    // Input identification: element-count match (confirmed by R7 diag), positional fallback.
    const float* x = nullptr;
    const float* W0 = nullptr;
    const float* Ws = nullptr;
    const float* bs = nullptr;
    const float* lin_w = nullptr;
    const float* lin_b = nullptr;
    const int*   ei = nullptr;
    for (int i = 0; i < n_in; i++) {
        switch (in_sizes[i]) {
            case 12800000: x     = (const float*)d_in[i]; break;
            case 8192:     W0    = (const float*)d_in[i]; break;
            case 28672:    Ws    = (const float*)d_in[i]; break;
            case 512:      bs    = (const float*)d_in[i]; break;
            case 20480:    lin_w = (const float*)d_in[i]; break;
            case 40:       lin_b = (const float*)d_in[i]; break;
            case 3200000:
            case 6400000:  ei    = (const int*)d_in[i];   break;
            default: break;
        }
    }
    if (!(x && W0 && Ws && bs && lin_w && lin_b && ei)) {
        x     = (const float*)d_in[0];
        W0    = (const float*)d_in[1];
        Ws    = (const float*)d_in[2];
        bs    = (const float*)d_in[3];
        lin_w = (const float*)d_in[4];
        lin_b = (const float*)d_in[5];
        ei    = (const int*)d_in[6];
    }
    float* out = (float*)d_out;

    // ROOT-CAUSE FIX (R7): __device__ symbols used as HOST-side kernel args decay
    // to the host shadow address; on GB300 (ATS) the GEMM then silently writes to
    // host memory. Resolve true device addresses via cudaGetSymbolAddress.
    float* tmp_d = nullptr;
    float* h_d   = nullptr;
    cudaGetSymbolAddress((void**)&tmp_d, g_tmp);
    cudaGetSymbolAddress((void**)&h_d, g_h);

    cudaStreamCaptureStatus cs = cudaStreamCaptureStatusNone;
    cudaError_t qe = cudaStreamIsCapturing((cudaStream_t)0, &cs);
    bool capturing = (qe != cudaSuccess) || (cs != cudaStreamCaptureStatusNone);
    if (qe != cudaSuccess) (void)cudaGetLastError();

    const int NB = (Nn + 1023) / 1024;  // 98

    k_detect<<<1, 256>>>((const unsigned int*)ei);
    k_init_deg<<<(Nn + 255) / 256, 256>>>();
    k_count<<<(Ee + 255) / 256, 256>>>(ei);
    k_dis<<<(Nn + 255) / 256, 256>>>();
    k_scan_block<<<NB, 1024>>>();
    k_scan_bsum<<<1, 128>>>(NB);
    k_add_off<<<NB, 1024>>>();
    k_fill<<<(Ee + 255) / 256, 256>>>(ei);

    int outn = out_size > 0 ? out_size : Nn * OUTD;
    k_init_out<<<(outn + 255) / 256, 256>>>(out, lin_b, outn);

    const int GEMM_GRID = (Nn + 127) / 128;  // 782
    const int AGG_GRID = (Nn + 7) / 8;

    for (int l = 0; l < Ll; l++) {
        if (l == 0)
            k_gemm<INF, Hd, false><<<GEMM_GRID, 256>>>(x, W0, tmp_d);
        else
            k_gemm<Hd, Hd, false><<<GEMM_GRID, 256>>>(h_d, Ws + (size_t)(l - 1) * Hd * Hd, tmp_d);
        k_aggregate<<<AGG_GRID, 256>>>(bs + l * Hd);
        k_gemm<Hd, OUTD, true><<<GEMM_GRID, 256>>>(h_d, lin_w + (size_t)l * Hd * OUTD, out);
    }

    // -------- zero-output tripwire (correctness call only; never during capture) --------
    if (!capturing) {
        static float ho[8];
        cudaMemcpyAsync(ho, out, 8 * sizeof(float), cudaMemcpyDeviceToHost, 0);
        cudaError_t qs = cudaErrorNotReady;
        for (long it = 0; it < 4000000000L; it++) {
            qs = cudaStreamQuery((cudaStream_t)0);
            if (qs != cudaErrorNotReady) break;
        }
        float mx = 0.f;
        for (int i = 0; i < 8; i++) mx = fmaxf(mx, fabsf(ho[i]));
        if (qs != cudaSuccess || mx < 1e-6f) {
            static float hf[8];
            cudaMemcpyFromSymbolAsync(hf, g_tmp, 4 * sizeof(float), 0, cudaMemcpyDeviceToHost, 0);
            cudaMemcpyFromSymbolAsync(hf + 4, g_h, 4 * sizeof(float), 0, cudaMemcpyDeviceToHost, 0);
            cudaError_t q2 = cudaErrorNotReady;
            for (long it = 0; it < 4000000000L; it++) {
                q2 = cudaStreamQuery((cudaStream_t)0);
                if (q2 != cudaErrorNotReady) break;
            }
            fprintf(stderr,
                    "[diag] TRIPWIRE mx=%g q=%s tmp=%g %g %g %g h=%g %g %g %g "
                    "tmp_d=%p h_d=%p out=%g %g %g %g\n",
                    mx, cudaGetErrorName(qs), hf[0], hf[1], hf[2], hf[3], hf[4], hf[5],
                    hf[6], hf[7], (void*)tmp_d, (void*)h_d, ho[0], ho[1], ho[2], ho[3]);
            fflush(stderr);
            abort();  // force rc!=0 so the harness surfaces this dump
        }
    }
}

// round 10
// speedup vs baseline: 1.0566x; 1.0566x over previous
#include <cuda_runtime.h>
#include <cuda_fp16.h>
#include <cstdio>
#include <cstdlib>
#include <cstdint>
#include <cmath>

#define Nn   100000
#define Ee   1600000
#define INF  128
#define Hd   64
#define Ll   8
#define OUTD 40

// ---------------- scratch (static device globals; no allocation) ----------------
__device__ int   g_deg[Nn];
__device__ float g_dis[Nn];
__device__ int   g_rowptr[Nn + 1];
__device__ int   g_cursor[Nn];
__device__ __align__(16) int2   g_ew[Ee];                 // {src, float_bits(norm)}
__device__ int   g_bsum[128];
__device__ __align__(16) __half g_tmp[(size_t)Nn * Hd];   // h @ W (fp16, gather payload)
__device__ __align__(16) float  g_h[(size_t)Nn * Hd];     // layer output (fp32)
__device__ int   g_is64;

// ---------------- dtype probe: int64 vs int32 edge_index ----------------
__global__ void k_detect(const unsigned int* __restrict__ p) {
    __shared__ unsigned int s;
    if (threadIdx.x == 0) s = 0u;
    __syncthreads();
    unsigned int v = 0u;
    for (int e = threadIdx.x; e < 2048; e += 256) v |= p[2 * e + 1];
    atomicOr(&s, v);
    __syncthreads();
    if (threadIdx.x == 0) g_is64 = (s == 0u) ? 1 : 0;
}
__device__ __forceinline__ int ld_src(const int* p, int e) {
    return g_is64 ? p[2 * e] : p[e];
}
__device__ __forceinline__ int ld_dst(const int* p, int e) {
    return g_is64 ? p[2 * Ee + 2 * e] : p[Ee + e];
}

// ---------------- degree / normalization ----------------
__global__ void k_count(const int* __restrict__ ei) {
    int e = blockIdx.x * 256 + threadIdx.x;
    if (e < Ee) atomicAdd(&g_deg[ld_dst(ei, e)], 1);
}
__global__ void k_dis() {
    int i = blockIdx.x * 256 + threadIdx.x;
    if (i < Nn) g_dis[i] = rsqrtf((float)(g_deg[i] + 1));  // +1 self loop
}

// ---------------- CSR build: exclusive scan of deg (edges only) ----------------
__global__ void k_scan_block() {
    __shared__ int s[1024];
    int i = blockIdx.x * 1024 + threadIdx.x;
    int v = (i < Nn) ? g_deg[i] : 0;
    s[threadIdx.x] = v;
    __syncthreads();
    for (int off = 1; off < 1024; off <<= 1) {
        int t = (threadIdx.x >= off) ? s[threadIdx.x - off] : 0;
        __syncthreads();
        s[threadIdx.x] += t;
        __syncthreads();
    }
    if (i < Nn) g_rowptr[i] = s[threadIdx.x] - v;
    if (threadIdx.x == 1023) g_bsum[blockIdx.x] = s[1023];
}
__global__ void k_scan_bsum(int nb) {
    __shared__ int s[128];
    int v = (threadIdx.x < nb) ? g_bsum[threadIdx.x] : 0;
    s[threadIdx.x] = v;
    __syncthreads();
    for (int off = 1; off < 128; off <<= 1) {
        int t = (threadIdx.x >= off) ? s[threadIdx.x - off] : 0;
        __syncthreads();
        s[threadIdx.x] += t;
        __syncthreads();
    }
    if (threadIdx.x < nb) g_bsum[threadIdx.x] = s[threadIdx.x] - v;
}
__global__ void k_add_off() {
    int i = blockIdx.x * 1024 + threadIdx.x;
    if (i < Nn) {
        int r = g_rowptr[i] + g_bsum[blockIdx.x];
        g_rowptr[i] = r;
        g_cursor[i] = r;
    }
    if (i == 0) g_rowptr[Nn] = Ee;
}
__global__ void k_fill(const int* __restrict__ ei) {
    int e = blockIdx.x * 256 + threadIdx.x;
    if (e >= Ee) return;
    int s = ld_src(ei, e);
    int d = ld_dst(ei, e);
    int p = atomicAdd(&g_cursor[d], 1);
    g_ew[p] = make_int2(s, __float_as_int(g_dis[s] * g_dis[d]));
}

// ---------------- GEMM0: tmp[fp16] = x[N,128] @ W0[128,64] ----------------
// 128-row tile, 256 thr (16x16), 8x4 acc; col map j -> 2*tc+(j&1)+32*(j>>1)
__global__ void k_gemm0(const float* __restrict__ A, const float* __restrict__ B,
                        __half2* __restrict__ C) {
    constexpr int K = 128, KT = 32;
    __shared__ float sA[128][KT + 1];
    __shared__ float sB[KT][64];
    const int row0 = blockIdx.x * 128;
    const int tid = threadIdx.x, tr = tid >> 4, tc = tid & 15;
    float acc[8][4];
#pragma unroll
    for (int i = 0; i < 8; i++)
#pragma unroll
        for (int j = 0; j < 4; j++) acc[i][j] = 0.f;

    for (int k0 = 0; k0 < K; k0 += KT) {
#pragma unroll
        for (int t = 0; t < 4; t++) {
            int fi = tid + t * 256;
            int r = fi >> 3, c4 = fi & 7;
            float4 v = make_float4(0.f, 0.f, 0.f, 0.f);
            if (row0 + r < Nn)
                v = *(const float4*)&A[(size_t)(row0 + r) * K + k0 + c4 * 4];
            sA[r][c4 * 4 + 0] = v.x; sA[r][c4 * 4 + 1] = v.y;
            sA[r][c4 * 4 + 2] = v.z; sA[r][c4 * 4 + 3] = v.w;
        }
#pragma unroll
        for (int t = 0; t < 8; t++) {
            int fi = tid + t * 256;
            sB[fi >> 6][fi & 63] = B[(k0 + (fi >> 6)) * 64 + (fi & 63)];
        }
        __syncthreads();
#pragma unroll
        for (int kk = 0; kk < KT; kk++) {
            float a[8], b[4];
#pragma unroll
            for (int i = 0; i < 8; i++) a[i] = sA[tr + 16 * i][kk];
#pragma unroll
            for (int j = 0; j < 4; j++) b[j] = sB[kk][2 * tc + (j & 1) + 32 * (j >> 1)];
#pragma unroll
            for (int i = 0; i < 8; i++)
#pragma unroll
                for (int j = 0; j < 4; j++) acc[i][j] += a[i] * b[j];
        }
        __syncthreads();
    }
#pragma unroll
    for (int i = 0; i < 8; i++) {
        int r = row0 + tr + 16 * i;
        if (r >= Nn) continue;
        C[(size_t)r * 32 + tc]      = __floats2half2_rn(acc[i][0], acc[i][1]);
        C[(size_t)r * 32 + 16 + tc] = __floats2half2_rn(acc[i][2], acc[i][3]);
    }
}

// ---------------- fused GEMM: tmp[fp16] = h@W (64) ; out (+)= h@LW (40) ----------------
template <bool FIRST>
__global__ void k_gemm_fused(const float* __restrict__ A, const float* __restrict__ W,
                             const float* __restrict__ LW, __half2* __restrict__ C1,
                             float* __restrict__ out, const float* __restrict__ lin_b) {
    constexpr int K = 64, KT = 32, NC = 112;  // 104 cols padded to 112
    __shared__ float sA[128][KT + 1];
    __shared__ float sB[KT][NC];
    const int row0 = blockIdx.x * 128;
    const int tid = threadIdx.x, tr = tid >> 4, tc = tid & 15;
    float acc[8][7];
#pragma unroll
    for (int i = 0; i < 8; i++)
#pragma unroll
        for (int j = 0; j < 7; j++) acc[i][j] = 0.f;

    for (int k0 = 0; k0 < K; k0 += KT) {
#pragma unroll
        for (int t = 0; t < 4; t++) {
            int fi = tid + t * 256;
            int r = fi >> 3, c4 = fi & 7;
            float4 v = make_float4(0.f, 0.f, 0.f, 0.f);
            if (row0 + r < Nn)
                v = *(const float4*)&A[(size_t)(row0 + r) * K + k0 + c4 * 4];
            sA[r][c4 * 4 + 0] = v.x; sA[r][c4 * 4 + 1] = v.y;
            sA[r][c4 * 4 + 2] = v.z; sA[r][c4 * 4 + 3] = v.w;
        }
        // sB: 32 x 112  (cols 0..63 = W, 64..103 = LW, rest 0)
        for (int fi = tid; fi < KT * NC; fi += 256) {
            int kk = fi / NC, c = fi % NC;
            float v = 0.f;
            if (c < 64) v = W[(k0 + kk) * 64 + c];
            else if (c < 104) v = LW[(k0 + kk) * OUTD + (c - 64)];
            sB[kk][c] = v;
        }
        __syncthreads();
#pragma unroll
        for (int kk = 0; kk < KT; kk++) {
            float a[8], b[7];
#pragma unroll
            for (int i = 0; i < 8; i++) a[i] = sA[tr + 16 * i][kk];
#pragma unroll
            for (int j = 0; j < 4; j++) b[j] = sB[kk][2 * tc + (j & 1) + 32 * (j >> 1)];
#pragma unroll
            for (int j = 4; j < 7; j++) b[j] = sB[kk][64 + tc + 16 * (j - 4)];
#pragma unroll
            for (int i = 0; i < 8; i++)
#pragma unroll
                for (int j = 0; j < 7; j++) acc[i][j] += a[i] * b[j];
        }
        __syncthreads();
    }
#pragma unroll
    for (int i = 0; i < 8; i++) {
        int r = row0 + tr + 16 * i;
        if (r >= Nn) continue;
        C1[(size_t)r * 32 + tc]      = __floats2half2_rn(acc[i][0], acc[i][1]);
        C1[(size_t)r * 32 + 16 + tc] = __floats2half2_rn(acc[i][2], acc[i][3]);
#pragma unroll
        for (int j = 4; j < 7; j++) {
            int oc = tc + 16 * (j - 4);
            if (oc < OUTD) {
                if (FIRST) out[(size_t)r * OUTD + oc] = acc[i][j] + lin_b[oc];
                else       out[(size_t)r * OUTD + oc] += acc[i][j];
            }
        }
    }
}

// ---------------- JK-only GEMM (last layer): out += h @ lin_w[7] ----------------
__global__ void k_gemm_jk(const float* __restrict__ A, const float* __restrict__ B,
                          float* __restrict__ C) {
    constexpr int K = 64, KT = 32;
    __shared__ float sA[128][KT + 1];
    __shared__ float sB[KT][64];
    const int row0 = blockIdx.x * 128;
    const int tid = threadIdx.x, tr = tid >> 4, tc = tid & 15;
    float acc[8][4];
#pragma unroll
    for (int i = 0; i < 8; i++)
#pragma unroll
        for (int j = 0; j < 4; j++) acc[i][j] = 0.f;

    for (int k0 = 0; k0 < K; k0 += KT) {
#pragma unroll
        for (int t = 0; t < 4; t++) {
            int fi = tid + t * 256;
            int r = fi >> 3, c4 = fi & 7;
            float4 v = make_float4(0.f, 0.f, 0.f, 0.f);
            if (row0 + r < Nn)
                v = *(const float4*)&A[(size_t)(row0 + r) * K + k0 + c4 * 4];
            sA[r][c4 * 4 + 0] = v.x; sA[r][c4 * 4 + 1] = v.y;
            sA[r][c4 * 4 + 2] = v.z; sA[r][c4 * 4 + 3] = v.w;
        }
#pragma unroll
        for (int t = 0; t < 8; t++) {
            int fi = tid + t * 256;
            int kk = fi >> 6, c = fi & 63;
            sB[kk][c] = (c < OUTD) ? B[(k0 + kk) * OUTD + c] : 0.f;
        }
        __syncthreads();
#pragma unroll
        for (int kk = 0; kk < KT; kk++) {
            float a[8], b[4];
#pragma unroll
            for (int i = 0; i < 8; i++) a[i] = sA[tr + 16 * i][kk];
#pragma unroll
            for (int j = 0; j < 4; j++) b[j] = sB[kk][tc + 16 * j];
#pragma unroll
            for (int i = 0; i < 8; i++)
#pragma unroll
                for (int j = 0; j < 4; j++) acc[i][j] += a[i] * b[j];
        }
        __syncthreads();
    }
#pragma unroll
    for (int i = 0; i < 8; i++) {
        int r = row0 + tr + 16 * i;
        if (r >= Nn) continue;
#pragma unroll
        for (int j = 0; j < 4; j++) {
            int c = tc + 16 * j;
            if (c < OUTD) C[(size_t)r * OUTD + c] += acc[i][j];
        }
    }
}

// ---------------- sparse aggregation: h = relu(A_hat * tmp + b), tmp fp16 ----------------
__global__ void k_aggregate(const float* __restrict__ bias) {
    int node = blockIdx.x * 8 + (threadIdx.x >> 5);
    if (node >= Nn) return;
    int lane = threadIdx.x & 31;
    const __half2* tp = (const __half2*)g_tmp;
    float ax = 0.f, ay = 0.f;
    int beg = g_rowptr[node], end = g_rowptr[node + 1];
    for (int j = beg; j < end; j++) {
        int2 e = __ldg(&g_ew[j]);
        float wt = __int_as_float(e.y);
        float2 v = __half22float2(tp[(size_t)e.x * 32 + lane]);
        ax += wt * v.x;
        ay += wt * v.y;
    }
    float d = g_dis[node];
    float sw = d * d;
    float2 v = __half22float2(tp[(size_t)node * 32 + lane]);
    ax += sw * v.x;
    ay += sw * v.y;
    ax += bias[2 * lane];
    ay += bias[2 * lane + 1];
    float2 r;
    r.x = fmaxf(ax, 0.f);
    r.y = fmaxf(ay, 0.f);
    *(float2*)&g_h[(size_t)node * Hd + 2 * lane] = r;
}

extern "C" void kernel_launch(void* const* d_in, const int* in_sizes, int n_in,
                              void* d_out, int out_size) {
    const float* x = nullptr;
    const float* W0 = nullptr;
    const float* Ws = nullptr;
    const float* bs = nullptr;
    const float* lin_w = nullptr;
    const float* lin_b = nullptr;
    const int*   ei = nullptr;
    for (int i = 0; i < n_in; i++) {
        switch (in_sizes[i]) {
            case 12800000: x     = (const float*)d_in[i]; break;
            case 8192:     W0    = (const float*)d_in[i]; break;
            case 28672:    Ws    = (const float*)d_in[i]; break;
            case 512:      bs    = (const float*)d_in[i]; break;
            case 20480:    lin_w = (const float*)d_in[i]; break;
            case 40:       lin_b = (const float*)d_in[i]; break;
            case 3200000:
            case 6400000:  ei    = (const int*)d_in[i];   break;
            default: break;
        }
    }
    if (!(x && W0 && Ws && bs && lin_w && lin_b && ei)) {
        x     = (const float*)d_in[0];
        W0    = (const float*)d_in[1];
        Ws    = (const float*)d_in[2];
        bs    = (const float*)d_in[3];
        lin_w = (const float*)d_in[4];
        lin_b = (const float*)d_in[5];
        ei    = (const int*)d_in[6];
    }
    float* out = (float*)d_out;

    // device-symbol addresses for host-side kernel args (R7 root cause)
    __half2* tmp_d = nullptr;
    float*   h_d   = nullptr;
    int*     deg_d = nullptr;
    cudaGetSymbolAddress((void**)&tmp_d, g_tmp);
    cudaGetSymbolAddress((void**)&h_d, g_h);
    cudaGetSymbolAddress((void**)&deg_d, g_deg);

    cudaStreamCaptureStatus cs = cudaStreamCaptureStatusNone;
    cudaError_t qe = cudaStreamIsCapturing((cudaStream_t)0, &cs);
    bool capturing = (qe != cudaSuccess) || (cs != cudaStreamCaptureStatusNone);
    if (qe != cudaSuccess) (void)cudaGetLastError();

    const int NB = (Nn + 1023) / 1024;  // 98
    const int GEMM_GRID = (Nn + 127) / 128;  // 782
    const int AGG_GRID = (Nn + 7) / 8;

    k_detect<<<1, 256>>>((const unsigned int*)ei);
    cudaMemsetAsync(deg_d, 0, Nn * sizeof(int), 0);
    k_count<<<(Ee + 255) / 256, 256>>>(ei);
    k_dis<<<(Nn + 255) / 256, 256>>>();
    k_scan_block<<<NB, 1024>>>();
    k_scan_bsum<<<1, 128>>>(NB);
    k_add_off<<<NB, 1024>>>();
    k_fill<<<(Ee + 255) / 256, 256>>>(ei);

    k_gemm0<<<GEMM_GRID, 256>>>(x, W0, tmp_d);
    for (int l = 0; l < Ll; l++) {
        k_aggregate<<<AGG_GRID, 256>>>(bs + l * Hd);
        if (l < Ll - 1) {
            if (l == 0)
                k_gemm_fused<true><<<GEMM_GRID, 256>>>(h_d, Ws + (size_t)l * Hd * Hd,
                                                       lin_w + (size_t)l * Hd * OUTD,
                                                       tmp_d, out, lin_b);
            else
                k_gemm_fused<false><<<GEMM_GRID, 256>>>(h_d, Ws + (size_t)l * Hd * Hd,
                                                        lin_w + (size_t)l * Hd * OUTD,
                                                        tmp_d, out, lin_b);
        } else {
            k_gemm_jk<<<GEMM_GRID, 256>>>(h_d, lin_w + (size_t)l * Hd * OUTD, out);
        }
    }

    // -------- zero-output tripwire (correctness call only; never during capture) --------
    if (!capturing) {
        static float ho[8];
        cudaMemcpyAsync(ho, out, 8 * sizeof(float), cudaMemcpyDeviceToHost, 0);
        cudaError_t qs = cudaErrorNotReady;
        for (long it = 0; it < 4000000000L; it++) {
            qs = cudaStreamQuery((cudaStream_t)0);
            if (qs != cudaErrorNotReady) break;
        }
        float mx = 0.f;
        for (int i = 0; i < 8; i++) mx = fmaxf(mx, fabsf(ho[i]));
        if (qs != cudaSuccess || mx < 1e-6f) {
            fprintf(stderr, "[diag] TRIPWIRE mx=%g q=%s out=%g %g %g %g\n", mx,
                    cudaGetErrorName(qs), ho[0], ho[1], ho[2], ho[3]);
            fflush(stderr);
            abort();
        }
    }
}